// round 15
// baseline (speedup 1.0000x reference)
#include <cuda_runtime.h>
#include <math.h>

#define BSZ 2
#define SEQ 2048
#define EMB 1024
#define NH  16
#define HD  64
#define MROWS (BSZ * SEQ)          /* 4096 */
#define NQG   (NH * HD + NH)       /* 1040: Wq/bq cols (Q 0..1023, gates 1024..1039) */

typedef unsigned long long u64;

// ---- packed f32x2 helpers (Blackwell PTX) ----
__device__ __forceinline__ u64 ffma2(u64 a, u64 b, u64 c) {
    u64 d; asm("fma.rn.f32x2 %0, %1, %2, %3;" : "=l"(d) : "l"(a), "l"(b), "l"(c));
    return d;
}
__device__ __forceinline__ u64 fmul2(u64 a, u64 b) {
    u64 d; asm("mul.rn.f32x2 %0, %1, %2;" : "=l"(d) : "l"(a), "l"(b));
    return d;
}
__device__ __forceinline__ u64 bcast2(float x) {
    u64 d; unsigned xu = __float_as_uint(x);
    asm("mov.b64 %0, {%1, %1};" : "=l"(d) : "r"(xu));
    return d;
}
__device__ __forceinline__ float2 unpack2(u64 p) {
    unsigned lo, hi; asm("mov.b64 {%0, %1}, %2;" : "=r"(lo), "=r"(hi) : "l"(p));
    return make_float2(__uint_as_float(lo), __uint_as_float(hi));
}

// Scratch (static device globals — no allocation allowed anywhere)
__device__ float g_Q   [MROWS * EMB];
__device__ float g_Gate[MROWS * NH];
__device__ float g_K   [MROWS * EMB];
__device__ float g_V   [MROWS * EMB];
__device__ float g_AO  [MROWS * EMB];

// ---------------------------------------------------------------------------
// SGEMM 128x128x16 (measured 174 us per 1024-col GEMM).
// MODE 0: fused QKV (blockIdx.z selects), MODE 1: out = g_AO @ Wo + bo
// ---------------------------------------------------------------------------
template<int MODE>
__global__ __launch_bounds__(256, 2)
void sgemm128(const float* __restrict__ X,
              const float* __restrict__ W0, const float* __restrict__ b0,
              const float* __restrict__ W1, const float* __restrict__ b1,
              const float* __restrict__ W2, const float* __restrict__ b2,
              float* __restrict__ outp)
{
    const float* A; const float* B; const float* bias; float* C; int ldb;
    if (MODE == 0) {
        A = X;
        const int z = blockIdx.z;
        if (z == 0)      { B = W0; bias = b0; C = g_Q; ldb = NQG; }
        else if (z == 1) { B = W1; bias = b1; C = g_K; ldb = EMB; }
        else             { B = W2; bias = b2; C = g_V; ldb = EMB; }
    } else {
        A = g_AO; B = W0; bias = b0; C = outp; ldb = EMB;
    }

    __shared__ float As[16][132];
    __shared__ float Bs[16][132];

    const int tid = threadIdx.x;
    const int tx = tid & 15;
    const int ty = tid >> 4;
    const int row0 = blockIdx.y * 128;
    const int col0 = blockIdx.x * 128;

    const int arow = tid >> 2;
    const int akc  = (tid & 3) << 2;
    const int brow = tid >> 5;
    const int bcol = (tid & 31) << 2;

    float4 pa0, pa1, pb0, pb1;

    pa0 = *(const float4*)&A[(size_t)(row0 + arow) * EMB + akc];
    pa1 = *(const float4*)&A[(size_t)(row0 + arow + 64) * EMB + akc];
    pb0 = *(const float4*)&B[(size_t)(brow) * ldb + col0 + bcol];
    pb1 = *(const float4*)&B[(size_t)(brow + 8) * ldb + col0 + bcol];

    u64 acc2[8][4] = {};

    for (int kb = 0; kb < EMB; kb += 16) {
        __syncthreads();
        As[akc + 0][arow] = pa0.x;  As[akc + 1][arow] = pa0.y;
        As[akc + 2][arow] = pa0.z;  As[akc + 3][arow] = pa0.w;
        As[akc + 0][arow + 64] = pa1.x;  As[akc + 1][arow + 64] = pa1.y;
        As[akc + 2][arow + 64] = pa1.z;  As[akc + 3][arow + 64] = pa1.w;
        *(float4*)&Bs[brow][bcol]     = pb0;
        *(float4*)&Bs[brow + 8][bcol] = pb1;
        __syncthreads();

        if (kb + 16 < EMB) {
            pa0 = *(const float4*)&A[(size_t)(row0 + arow) * EMB + kb + 16 + akc];
            pa1 = *(const float4*)&A[(size_t)(row0 + arow + 64) * EMB + kb + 16 + akc];
            pb0 = *(const float4*)&B[(size_t)(kb + 16 + brow) * ldb + col0 + bcol];
            pb1 = *(const float4*)&B[(size_t)(kb + 16 + brow + 8) * ldb + col0 + bcol];
        }

#pragma unroll
        for (int k = 0; k < 16; ++k) {
            const float4 a0 = *(const float4*)&As[k][ty * 4];
            const float4 a1 = *(const float4*)&As[k][64 + ty * 4];
            const ulonglong2 bq0 = *(const ulonglong2*)&Bs[k][tx * 4];
            const ulonglong2 bq1 = *(const ulonglong2*)&Bs[k][64 + tx * 4];
            u64 rb[4]; rb[0] = bq0.x; rb[1] = bq0.y; rb[2] = bq1.x; rb[3] = bq1.y;
            u64 ra[8];
            ra[0] = bcast2(a0.x); ra[1] = bcast2(a0.y);
            ra[2] = bcast2(a0.z); ra[3] = bcast2(a0.w);
            ra[4] = bcast2(a1.x); ra[5] = bcast2(a1.y);
            ra[6] = bcast2(a1.z); ra[7] = bcast2(a1.w);
#pragma unroll
            for (int i = 0; i < 8; ++i)
#pragma unroll
                for (int j = 0; j < 4; ++j)
                    acc2[i][j] = ffma2(ra[i], rb[j], acc2[i][j]);
        }
    }

#pragma unroll
    for (int ih = 0; ih < 2; ++ih) {
#pragma unroll
        for (int i = 0; i < 4; ++i) {
            const int row = row0 + ih * 64 + ty * 4 + i;
#pragma unroll
            for (int jh = 0; jh < 2; ++jh) {
                const int col = col0 + jh * 64 + tx * 4;
                const float2 p0 = unpack2(acc2[ih * 4 + i][jh * 2 + 0]);
                const float2 p1 = unpack2(acc2[ih * 4 + i][jh * 2 + 1]);
                float4 o;
                o.x = p0.x + bias[col + 0];
                o.y = p0.y + bias[col + 1];
                o.z = p1.x + bias[col + 2];
                o.w = p1.y + bias[col + 3];
                *(float4*)&C[(size_t)row * EMB + col] = o;
            }
        }
    }
}

// ---------------------------------------------------------------------------
// Gate kernel: g_Gate[row][h] = sigmoid(X[row] . Wq[:, 1024+h] + bq[1024+h]).
// ---------------------------------------------------------------------------
__global__ __launch_bounds__(128)
void gate_proj(const float* __restrict__ X, const float* __restrict__ Wq,
               const float* __restrict__ bq)
{
    const int warp = threadIdx.x >> 5;
    const int lane = threadIdx.x & 31;
    const int row  = blockIdx.x * 4 + warp;

    float acc[16] = {};
    for (int e = lane; e < EMB; e += 32) {
        const float xv = X[(size_t)row * EMB + e];
        const float* wrow = &Wq[(size_t)e * NQG + NH * HD];
        const float4 w0 = *(const float4*)&wrow[0];
        const float4 w1 = *(const float4*)&wrow[4];
        const float4 w2 = *(const float4*)&wrow[8];
        const float4 w3 = *(const float4*)&wrow[12];
        acc[0]  = fmaf(xv, w0.x, acc[0]);  acc[1]  = fmaf(xv, w0.y, acc[1]);
        acc[2]  = fmaf(xv, w0.z, acc[2]);  acc[3]  = fmaf(xv, w0.w, acc[3]);
        acc[4]  = fmaf(xv, w1.x, acc[4]);  acc[5]  = fmaf(xv, w1.y, acc[5]);
        acc[6]  = fmaf(xv, w1.z, acc[6]);  acc[7]  = fmaf(xv, w1.w, acc[7]);
        acc[8]  = fmaf(xv, w2.x, acc[8]);  acc[9]  = fmaf(xv, w2.y, acc[9]);
        acc[10] = fmaf(xv, w2.z, acc[10]); acc[11] = fmaf(xv, w2.w, acc[11]);
        acc[12] = fmaf(xv, w3.x, acc[12]); acc[13] = fmaf(xv, w3.y, acc[13]);
        acc[14] = fmaf(xv, w3.z, acc[14]); acc[15] = fmaf(xv, w3.w, acc[15]);
    }
#pragma unroll
    for (int h = 0; h < 16; ++h) {
#pragma unroll
        for (int off = 16; off >= 1; off >>= 1)
            acc[h] += __shfl_xor_sync(0xffffffffu, acc[h], off);
    }
    if (lane < 16) {
        const float logit = acc[lane] + bq[NH * HD + lane];
        g_Gate[(size_t)row * NH + lane] = 1.f / (1.f + __expf(-logit));
    }
}

// ---------------------------------------------------------------------------
// Flash attention + gate, v2: natural-layout smem with 16B-group XOR swizzle.
//   Qs [r][d] 64x64, Ks [c][d] 32x64, Vs [t][d] 32x64, Ps [r][t] 64x32 = 40KB
// Swizzle: float4-group g' = g ^ (row>>2); conflict-free in all hot loops.
// Scores are dot-products over d-pairs via FFMA2 (no broadcasts in score loop).
// grid = (32, 32), 128 threads, 3 syncs/iter, pk/pv prefetch issued at PV
// start so LDG latency hides under ~700 instrs and never overlaps score accs.
// ---------------------------------------------------------------------------
#define SWZ(row, g) ((g) ^ ((row) >> 2))              /* Qs/Ks/Vs: g 0..15 */
#define SWZP(row, g) ((g) ^ (((row) >> 2) & 7))       /* Ps: g 0..7 */

__global__ __launch_bounds__(128, 4)
void flash_gated(const float* __restrict__ mask)
{
    __shared__ float Qs[64 * 64];   // [r][d], scale pre-applied, swizzled
    __shared__ float Ks[32 * 64];   // [c][d], swizzled
    __shared__ float Vs[32 * 64];   // [t][d], swizzled
    __shared__ float Ps[64 * 32];   // [r][t], swizzled

    const int bh = blockIdx.y;
    const int b  = bh >> 4;
    const int h  = bh & 15;
    const int s0 = blockIdx.x * 64;

    const int tid = threadIdx.x;
    const int tx = tid & 7;    // score cols c4 = tx*4; PV d-cols d8 = tx*8
    const int ty = tid >> 3;   // score rows r4 = ty*4
    const int r4 = ty * 4;
    const int c4 = tx * 4;
    const int d8 = tx * 8;

    const float scale = 0.125f;

    // K/V tile load mapping: token c = lc + it*8 (it 0..3), float4-group lg
    const int lc = tid >> 4;           // 0..7
    const int lg = tid & 15;           // 0..15

    // ---- load Q tile (scaled) into Qs[r][d] swizzled ----
#pragma unroll
    for (int it = 0; it < 8; ++it) {
        const int r = (tid >> 4) + it * 8;       // 0..63
        float4 q = *(const float4*)&g_Q[(size_t)(b * SEQ + s0 + r) * EMB + h * HD + lg * 4];
        q.x *= scale; q.y *= scale; q.z *= scale; q.w *= scale;
        *(float4*)&Qs[r * 64 + SWZ(r, lg) * 4] = q;
    }

    u64 op[4][4] = {};                 // 4 rows x 4 d-pairs (d8..d8+7)
    float m[4], l[4];
#pragma unroll
    for (int i = 0; i < 4; ++i) { m[i] = -INFINITY; l[i] = 0.f; }

    // prologue: prefetch K/V tile 0
    float4 pk[4], pv[4];
#pragma unroll
    for (int it = 0; it < 4; ++it) {
        const int c = lc + it * 8;
        pk[it] = *(const float4*)&g_K[(size_t)(b * SEQ + c) * EMB + h * HD + lg * 4];
        pv[it] = *(const float4*)&g_V[(size_t)(b * SEQ + c) * EMB + h * HD + lg * 4];
    }

    for (int jt = 0; jt < SEQ / 32; ++jt) {
        const int t0 = jt * 32;
        __syncthreads();   // prev scores (Ks) + PV (Vs, Ps) reads done

        // ---- store prefetched K/V tiles (vector stores, swizzled) ----
#pragma unroll
        for (int it = 0; it < 4; ++it) {
            const int c = lc + it * 8;
            *(float4*)&Ks[c * 64 + SWZ(c, lg) * 4] = pk[it];
            *(float4*)&Vs[c * 64 + SWZ(c, lg) * 4] = pv[it];
        }
        __syncthreads();

        // ---- hoisted mask loads (covered by score loop) ----
        float4 mk[4];
#pragma unroll
        for (int i = 0; i < 4; ++i)
            mk[i] = *(const float4*)&mask[(size_t)(b * SEQ + s0 + r4 + i) * SEQ + t0 + c4];

        // ---- scores: dot-products over d-pairs, acc2[i][j] packs (even,odd) ----
        u64 acc2[4][4] = {};
#pragma unroll
        for (int dc = 0; dc < 16; ++dc) {          // d-chunk of 4 (one float4)
            ulonglong2 q[4];
#pragma unroll
            for (int i = 0; i < 4; ++i)
                q[i] = *(const ulonglong2*)&Qs[(r4 + i) * 64 + SWZ(r4 + i, dc) * 4];
#pragma unroll
            for (int j = 0; j < 4; ++j) {
                const ulonglong2 k = *(const ulonglong2*)&Ks[(c4 + j) * 64 + SWZ(c4 + j, dc) * 4];
#pragma unroll
                for (int i = 0; i < 4; ++i) {
                    acc2[i][j] = ffma2(q[i].x, k.x, acc2[i][j]);
                    acc2[i][j] = ffma2(q[i].y, k.y, acc2[i][j]);
                }
            }
        }

        // ---- horizontal add + mask ----
        float acc[4][4];
#pragma unroll
        for (int i = 0; i < 4; ++i) {
            float2 s0p = unpack2(acc2[i][0]);
            float2 s1p = unpack2(acc2[i][1]);
            float2 s2p = unpack2(acc2[i][2]);
            float2 s3p = unpack2(acc2[i][3]);
            acc[i][0] = s0p.x + s0p.y + mk[i].x;
            acc[i][1] = s1p.x + s1p.y + mk[i].y;
            acc[i][2] = s2p.x + s2p.y + mk[i].z;
            acc[i][3] = s3p.x + s3p.y + mk[i].w;
        }

        // ---- online softmax (8 lanes share a row) ----
        float fac[4];
#pragma unroll
        for (int i = 0; i < 4; ++i) {
            float lm = fmaxf(fmaxf(acc[i][0], acc[i][1]), fmaxf(acc[i][2], acc[i][3]));
#pragma unroll
            for (int off = 4; off >= 1; off >>= 1)
                lm = fmaxf(lm, __shfl_xor_sync(0xffffffffu, lm, off, 8));
            const float mn = fmaxf(m[i], lm);
            fac[i] = __expf(m[i] - mn);
            float rs = 0.f;
#pragma unroll
            for (int j = 0; j < 4; ++j) {
                acc[i][j] = __expf(acc[i][j] - mn);
                rs += acc[i][j];
            }
#pragma unroll
            for (int off = 4; off >= 1; off >>= 1)
                rs += __shfl_xor_sync(0xffffffffu, rs, off, 8);
            l[i] = l[i] * fac[i] + rs;
            m[i] = mn;
        }

        // ---- store P natural [r][t] (1 STS.128 per row, swizzled) ----
#pragma unroll
        for (int i = 0; i < 4; ++i) {
            float4 p; p.x = acc[i][0]; p.y = acc[i][1]; p.z = acc[i][2]; p.w = acc[i][3];
            *(float4*)&Ps[(r4 + i) * 32 + SWZP(r4 + i, tx) * 4] = p;
        }
        __syncthreads();

        // ---- prefetch next K/V tile (latency hidden under PV loop) ----
        if (jt + 1 < SEQ / 32) {
            const int tn = t0 + 32;
#pragma unroll
            for (int it = 0; it < 4; ++it) {
                const int c = tn + lc + it * 8;
                pk[it] = *(const float4*)&g_K[(size_t)(b * SEQ + c) * EMB + h * HD + lg * 4];
                pv[it] = *(const float4*)&g_V[(size_t)(b * SEQ + c) * EMB + h * HD + lg * 4];
            }
        }

        // ---- O = O*fac + P @ V ----
#pragma unroll
        for (int i = 0; i < 4; ++i) {
            const u64 f2 = bcast2(fac[i]);
#pragma unroll
            for (int j = 0; j < 4; ++j)
                op[i][j] = fmul2(op[i][j], f2);
        }

#pragma unroll
        for (int tc = 0; tc < 8; ++tc) {           // t-chunk of 4
            float4 rp[4];
#pragma unroll
            for (int i = 0; i < 4; ++i)
                rp[i] = *(const float4*)&Ps[(r4 + i) * 32 + SWZP(r4 + i, tc) * 4];
#pragma unroll
            for (int u = 0; u < 4; ++u) {
                const int t = tc * 4 + u;
                const u64 vA0 = *(const u64*)&Vs[t * 64 + SWZ(t, 2 * tx) * 4];
                const u64 vA1 = *(const u64*)&Vs[t * 64 + SWZ(t, 2 * tx) * 4 + 2];
                const u64 vB0 = *(const u64*)&Vs[t * 64 + SWZ(t, 2 * tx + 1) * 4];
                const u64 vB1 = *(const u64*)&Vs[t * 64 + SWZ(t, 2 * tx + 1) * 4 + 2];
                const float pu0 = (u == 0) ? rp[0].x : (u == 1) ? rp[0].y : (u == 2) ? rp[0].z : rp[0].w;
                const float pu1 = (u == 0) ? rp[1].x : (u == 1) ? rp[1].y : (u == 2) ? rp[1].z : rp[1].w;
                const float pu2 = (u == 0) ? rp[2].x : (u == 1) ? rp[2].y : (u == 2) ? rp[2].z : rp[2].w;
                const float pu3 = (u == 0) ? rp[3].x : (u == 1) ? rp[3].y : (u == 2) ? rp[3].z : rp[3].w;
                const u64 pb0 = bcast2(pu0), pb1 = bcast2(pu1);
                const u64 pb2 = bcast2(pu2), pb3 = bcast2(pu3);
                op[0][0] = ffma2(pb0, vA0, op[0][0]);
                op[0][1] = ffma2(pb0, vA1, op[0][1]);
                op[0][2] = ffma2(pb0, vB0, op[0][2]);
                op[0][3] = ffma2(pb0, vB1, op[0][3]);
                op[1][0] = ffma2(pb1, vA0, op[1][0]);
                op[1][1] = ffma2(pb1, vA1, op[1][1]);
                op[1][2] = ffma2(pb1, vB0, op[1][2]);
                op[1][3] = ffma2(pb1, vB1, op[1][3]);
                op[2][0] = ffma2(pb2, vA0, op[2][0]);
                op[2][1] = ffma2(pb2, vA1, op[2][1]);
                op[2][2] = ffma2(pb2, vB0, op[2][2]);
                op[2][3] = ffma2(pb2, vB1, op[2][3]);
                op[3][0] = ffma2(pb3, vA0, op[3][0]);
                op[3][1] = ffma2(pb3, vA1, op[3][1]);
                op[3][2] = ffma2(pb3, vB0, op[3][2]);
                op[3][3] = ffma2(pb3, vB1, op[3][3]);
            }
        }
    }

    // ---- epilogue: 1/l, gate, store ----
    // op[i][0..1] cover d8..d8+3 (logical group 2tx), op[i][2..3] d8+4..d8+7.
#pragma unroll
    for (int i = 0; i < 4; ++i) {
        const int srow = b * SEQ + s0 + r4 + i;
        const float gate = g_Gate[(size_t)srow * NH + h];
        const float inv_l = gate / l[i];
        const float2 q0 = unpack2(op[i][0]);
        const float2 q1 = unpack2(op[i][1]);
        const float2 q2 = unpack2(op[i][2]);
        const float2 q3 = unpack2(op[i][3]);
        float4 oa, ob;
        oa.x = q0.x * inv_l; oa.y = q0.y * inv_l;
        oa.z = q1.x * inv_l; oa.w = q1.y * inv_l;
        ob.x = q2.x * inv_l; ob.y = q2.y * inv_l;
        ob.z = q3.x * inv_l; ob.w = q3.y * inv_l;
        *(float4*)&g_AO[(size_t)srow * EMB + h * HD + d8]     = oa;
        *(float4*)&g_AO[(size_t)srow * EMB + h * HD + d8 + 4] = ob;
    }
}

// ---------------------------------------------------------------------------
// kernel_launch: KERNEL LAUNCHES ONLY (graph-capture safe).
// ---------------------------------------------------------------------------
extern "C" void kernel_launch(void* const* d_in, const int* in_sizes, int n_in,
                              void* d_out, int out_size)
{
    const float* X    = (const float*)d_in[0];
    const float* mask = (const float*)d_in[1];
    const float* Wq   = (const float*)d_in[2];
    const float* bq   = (const float*)d_in[3];
    const float* Wk   = (const float*)d_in[4];
    const float* bk   = (const float*)d_in[5];
    const float* Wv   = (const float*)d_in[6];
    const float* bv   = (const float*)d_in[7];
    const float* Wo   = (const float*)d_in[8];
    const float* bo   = (const float*)d_in[9];
    float* out = (float*)d_out;

    sgemm128<0><<<dim3(EMB / 128, MROWS / 128, 3), 256>>>(
        X, Wq, bq, Wk, bk, Wv, bv, nullptr);
    gate_proj<<<MROWS / 4, 128>>>(X, Wq, bq);

    flash_gated<<<dim3(SEQ / 64, BSZ * NH), 128>>>(mask);

    sgemm128<1><<<dim3(EMB / 128, MROWS / 128, 1), 256>>>(
        nullptr, Wo, bo, nullptr, nullptr, nullptr, nullptr, out);
}